// round 5
// baseline (speedup 1.0000x reference)
#include <cuda_runtime.h>
#include <math.h>

// ---------------- problem constants ----------------
#define HIMG 256
#define WIMG 256
#define NPIX 65536            // HIMG*WIMG
#define CDIM 180
#define NHEADS 6
#define HD 30                 // CDIM / NHEADS
#define WS 16
#define OWS 24
#define PADW 4                // (OWS-WS)/2
#define NWIN 16               // windows per side
#define NQ 256                // WS*WS
#define NKEY 576              // OWS*OWS
#define MLPH 360

// ---------------- scratch (device globals; no allocation allowed) ----------------
__device__ float g_xn [NPIX*CDIM];
__device__ float g_q  [NPIX*CDIM];
__device__ float g_kv [NPIX*2*CDIM];
__device__ float g_biasT[NHEADS*NKEY*NQ];   // [head][key][query]
__device__ float g_ao [NPIX*CDIM];
__device__ float g_xo [NPIX*CDIM];
__device__ float g_xn2[NPIX*CDIM];
__device__ float g_mh [NPIX*MLPH];

// ---------------- LayerNorm: one warp per row of 180 ----------------
__global__ void ln_kernel(const float* __restrict__ x, const float* __restrict__ g,
                          const float* __restrict__ b, float* __restrict__ y) {
    int row  = blockIdx.x * blockDim.y + threadIdx.y;
    int lane = threadIdx.x;
    const float* xr = x + (size_t)row * CDIM;
    float v[6];
    float s = 0.f;
#pragma unroll
    for (int i = 0; i < 6; i++) {
        int d = lane + 32 * i;
        v[i] = (d < CDIM) ? xr[d] : 0.f;
        s += v[i];
    }
#pragma unroll
    for (int o = 16; o > 0; o >>= 1) s += __shfl_xor_sync(0xffffffffu, s, o);
    float mu = s * (1.f / CDIM);
    float vs = 0.f;
#pragma unroll
    for (int i = 0; i < 6; i++) {
        int d = lane + 32 * i;
        float dv = (d < CDIM) ? (v[i] - mu) : 0.f;
        vs += dv * dv;
    }
#pragma unroll
    for (int o = 16; o > 0; o >>= 1) vs += __shfl_xor_sync(0xffffffffu, vs, o);
    float inv = rsqrtf(vs * (1.f / CDIM) + 1e-5f);
    float* yr = y + (size_t)row * CDIM;
#pragma unroll
    for (int i = 0; i < 6; i++) {
        int d = lane + 32 * i;
        if (d < CDIM) yr[d] = g[d] * (v[i] - mu) * inv + b[d];
    }
}

// ---------------- bias precompute: biasT[h][k][q] = table[rpi[q,k], h] ----------------
__global__ void bias_kernel(const int* __restrict__ rpi, const float* __restrict__ table) {
    int k = blockIdx.x;       // 0..575
    int q = threadIdx.x;      // 0..255
    int t = rpi[q * NKEY + k];
#pragma unroll
    for (int h = 0; h < NHEADS; h++)
        g_biasT[((size_t)h * NKEY + k) * NQ + q] = table[t * NHEADS + h];
}

// ---------------- tf32 tensor-core GEMM, double-buffered, paired smem ----------------
// C = act(A@B + bias [+ res]). A: MxK row-major fp32, B: KxN row-major fp32.
// BM=128, BN=64, BK=32. 8 warps, each a 32x32 tile = 2x4 m16n8k8 mmas.
// Smem holds tf32 k-pairs (k, k+4) as uint2 so each fragment load is one LDS.64.
// Strides: A tq-stride 132, ks-plane 532 (banks 8ks+2m+sel: conflict-free stores,
// 8tq+2m reads). B tq-stride 68, ks-plane 273 (banks 2ks+8tq+sel stores, 8tq+2col
// reads) -- all conflict-free. Double-buffered with register staging.
// Requires M%128==0, N%4==0, K%4==0 (true for all five GEMMs).
__device__ __forceinline__ unsigned f2tf32(float v) {
    unsigned u;
    asm("cvt.rna.tf32.f32 %0, %1;" : "=r"(u) : "f"(v));
    return u;
}

#define AS_T  132
#define AS_KS 532
#define ABUF  2128      // 4*AS_KS (uint2)
#define BS_T  68
#define BS_KS 273
#define BBUF  1092      // 4*BS_KS (uint2)
#define STGSZ (ABUF + BBUF)               // 3220 uint2 per stage
#define GEMM_SMEM (2 * STGSZ * 8)         // 51520 bytes

template<int ACT>
__global__ void __launch_bounds__(256, 2) mma_gemm(
    const float* __restrict__ A, const float* __restrict__ B,
    const float* __restrict__ bias, const float* __restrict__ res,
    float* __restrict__ C, int M, int N, int K)
{
    extern __shared__ uint2 smbuf[];

    int bm = blockIdx.y * 128;
    int bn = blockIdx.x * 64;
    int t    = threadIdx.x;
    int lane = t & 31;
    int warp = t >> 5;
    int g  = lane >> 2;
    int tq = lane & 3;
    int wm = (warp >> 1) * 32;
    int wn = (warp & 1) * 32;

    float acc[2][4][4];
#pragma unroll
    for (int mi = 0; mi < 2; mi++)
#pragma unroll
        for (int ni = 0; ni < 4; ni++)
#pragma unroll
            for (int r = 0; r < 4; r++) acc[mi][ni][r] = 0.f;

    int kIters = (K + 31) >> 5;
    float4 ra[4], rb[2];

    // ---- global load of tile `it` into registers ----
    auto gload = [&](int it) {
        int k0 = it * 32;
#pragma unroll
        for (int i = 0; i < 4; i++) {
            int idx = t + 256 * i;
            int m = idx >> 3, j = idx & 7;
            int gk = k0 + 4 * j;
            ra[i] = (gk < K) ? *(const float4*)&A[(size_t)(bm + m) * K + gk]
                             : make_float4(0.f, 0.f, 0.f, 0.f);
        }
#pragma unroll
        for (int i = 0; i < 2; i++) {
            int idx = t + 256 * i;
            int k = idx & 31, n = 4 * (idx >> 5);
            int gk = k0 + k, gn = bn + n;
            rb[i] = (gk < K && gn < N) ? *(const float4*)&B[(size_t)gk * N + gn]
                                       : make_float4(0.f, 0.f, 0.f, 0.f);
        }
    };

    // ---- store staged registers (tf32) into smem stage s ----
    auto sstore = [&](int s) {
        unsigned* ab = (unsigned*)(smbuf + s * STGSZ);
        unsigned* bb = (unsigned*)(smbuf + s * STGSZ + ABUF);
#pragma unroll
        for (int i = 0; i < 4; i++) {
            int idx = t + 256 * i;
            int m = idx >> 3, j = idx & 7;
            int ks = j >> 1, sel = j & 1;
            unsigned base = 2 * (ks * AS_KS + m) + sel;
            ab[base + 2 * (0 * AS_T)] = f2tf32(ra[i].x);
            ab[base + 2 * (1 * AS_T)] = f2tf32(ra[i].y);
            ab[base + 2 * (2 * AS_T)] = f2tf32(ra[i].z);
            ab[base + 2 * (3 * AS_T)] = f2tf32(ra[i].w);
        }
#pragma unroll
        for (int i = 0; i < 2; i++) {
            int idx = t + 256 * i;
            int k = idx & 31, n = 4 * (idx >> 5);
            int ks = k >> 3, tqq = k & 3, sel = (k >> 2) & 1;
            unsigned base = 2 * (ks * BS_KS + tqq * BS_T + n) + sel;
            bb[base + 0] = f2tf32(rb[i].x);
            bb[base + 2] = f2tf32(rb[i].y);
            bb[base + 4] = f2tf32(rb[i].z);
            bb[base + 6] = f2tf32(rb[i].w);
        }
    };

    // ---- compute one stage: 4 k-steps x 8 mmas ----
    auto compute = [&](int s) {
        const uint2* as = smbuf + s * STGSZ;
        const uint2* bs = as + ABUF;
#pragma unroll
        for (int ks = 0; ks < 4; ks++) {
            uint2 aLo[2], aHi[2], bp[4];
#pragma unroll
            for (int mi = 0; mi < 2; mi++) {
                int m0 = wm + mi * 16 + g;
                aLo[mi] = as[ks * AS_KS + tq * AS_T + m0];
                aHi[mi] = as[ks * AS_KS + tq * AS_T + m0 + 8];
            }
#pragma unroll
            for (int ni = 0; ni < 4; ni++)
                bp[ni] = bs[ks * BS_KS + tq * BS_T + wn + ni * 8 + g];
#pragma unroll
            for (int mi = 0; mi < 2; mi++)
#pragma unroll
                for (int ni = 0; ni < 4; ni++) {
                    asm volatile(
                        "mma.sync.aligned.m16n8k8.row.col.f32.tf32.tf32.f32 "
                        "{%0,%1,%2,%3}, {%4,%5,%6,%7}, {%8,%9}, {%0,%1,%2,%3};"
                        : "+f"(acc[mi][ni][0]), "+f"(acc[mi][ni][1]),
                          "+f"(acc[mi][ni][2]), "+f"(acc[mi][ni][3])
                        : "r"(aLo[mi].x), "r"(aHi[mi].x),
                          "r"(aLo[mi].y), "r"(aHi[mi].y),
                          "r"(bp[ni].x), "r"(bp[ni].y));
                }
        }
    };

    gload(0);
    sstore(0);
    __syncthreads();
    for (int it = 0; it < kIters; it++) {
        if (it + 1 < kIters) gload(it + 1);
        compute(it & 1);
        if (it + 1 < kIters) {
            sstore((it + 1) & 1);
            __syncthreads();
        }
    }

    // ---- epilogue ----
#pragma unroll
    for (int mi = 0; mi < 2; mi++) {
#pragma unroll
        for (int ni = 0; ni < 4; ni++) {
            int n = bn + wn + ni * 8 + 2 * tq;
            if (n >= N) continue;
            float bn0 = bias[n], bn1 = bias[n + 1];
#pragma unroll
            for (int half = 0; half < 2; half++) {
                int m = bm + wm + mi * 16 + g + half * 8;
                float v0 = acc[mi][ni][half * 2 + 0] + bn0;
                float v1 = acc[mi][ni][half * 2 + 1] + bn1;
                if (res) {
                    v0 += res[(size_t)m * N + n];
                    v1 += res[(size_t)m * N + n + 1];
                }
                if (ACT == 1) {
                    v0 = v0 * normcdff(v0);
                    v1 = v1 * normcdff(v1);
                }
                C[(size_t)m * N + n]     = v0;
                C[(size_t)m * N + n + 1] = v1;
            }
        }
    }
}

// ---------------- windowed attention ----------------
// grid (256 windows, 6 heads), 256 threads = one per query.
// Scores are tiny (|s| << 1), so softmax without max-subtraction is safe.
// Zero-padded OOB keys contribute exp(bias) to the denominator with v=0.
__global__ void __launch_bounds__(256) attn_kernel() {
    int win  = blockIdx.x;
    int head = blockIdx.y;
    int wi = win >> 4, wj = win & 15;
    int t  = threadIdx.x;
    int qi = t >> 4, qj = t & 15;
    int r = wi * WS + qi, c = wj * WS + qj;

    const float scale = 0.18257418583505537f;  // 30^-0.5
    const float* qrow = g_q + ((size_t)(r * WIMG + c)) * CDIM + head * HD;
    float qv[HD];
#pragma unroll
    for (int d = 0; d < HD; d++) qv[d] = qrow[d] * scale;

    float l = 0.f;
    float o[HD];
#pragma unroll
    for (int d = 0; d < HD; d++) o[d] = 0.f;

    __shared__ float Ks[64][32];
    __shared__ float Vs[64][32];

    int half = t >> 7;             // 0: load K, 1: load V
    int kk_l = (t & 127) >> 1;     // key within chunk
    int part = t & 1;              // 15-float half of the head dim

    const float* biasBase = g_biasT + ((size_t)head * NKEY) * NQ + t;

    for (int ch = 0; ch < 9; ch++) {
        int cb = ch * 64;
        __syncthreads();
        {
            int key = cb + kk_l;
            int ki = key / OWS;
            int kj = key - ki * OWS;
            int gr = wi * WS - PADW + ki;
            int gc = wj * WS - PADW + kj;
            bool ok = ((unsigned)gr < HIMG) && ((unsigned)gc < WIMG);
            const float* src = g_kv + ((size_t)(gr * WIMG + gc)) * (2 * CDIM)
                               + half * CDIM + head * HD + part * 15;
            float* dst = (half ? &Vs[kk_l][0] : &Ks[kk_l][0]) + part * 15;
#pragma unroll
            for (int d = 0; d < 15; d++) dst[d] = ok ? src[d] : 0.f;
            if (part == 0) dst[30] = 0.f, dst[31] = 0.f;
        }
        __syncthreads();

#pragma unroll 4
        for (int kk = 0; kk < 64; kk++) {
            float bias = biasBase[(size_t)(cb + kk) * NQ];
            const float4* kp = (const float4*)&Ks[kk][0];
            float s0 = 0.f, s1 = 0.f, s2 = 0.f, s3 = 0.f;
#pragma unroll
            for (int g = 0; g < 7; g++) {
                float4 k4 = kp[g];
                s0 += qv[4 * g + 0] * k4.x;
                s1 += qv[4 * g + 1] * k4.y;
                s2 += qv[4 * g + 2] * k4.z;
                s3 += qv[4 * g + 3] * k4.w;
            }
            float2 kt = *(const float2*)&Ks[kk][28];
            s0 += qv[28] * kt.x;
            s1 += qv[29] * kt.y;
            float s = (s0 + s1) + (s2 + s3) + bias;
            float p = __expf(s);
            l += p;
            const float4* vp = (const float4*)&Vs[kk][0];
#pragma unroll
            for (int g = 0; g < 7; g++) {
                float4 v4 = vp[g];
                o[4 * g + 0] += p * v4.x;
                o[4 * g + 1] += p * v4.y;
                o[4 * g + 2] += p * v4.z;
                o[4 * g + 3] += p * v4.w;
            }
            float2 vt = *(const float2*)&Vs[kk][28];
            o[28] += p * vt.x;
            o[29] += p * vt.y;
        }
    }

    float invl = 1.f / l;
    float* orow = g_ao + ((size_t)(r * WIMG + c)) * CDIM + head * HD;
#pragma unroll
    for (int d = 0; d < HD; d++) orow[d] = o[d] * invl;
}

// ---------------- launch ----------------
extern "C" void kernel_launch(void* const* d_in, const int* in_sizes, int n_in,
                              void* d_out, int out_size) {
    const float* x    = (const float*)d_in[0];
    const int*   rpi  = (const int*)  d_in[1];
    const float* n1g  = (const float*)d_in[4];
    const float* n1b  = (const float*)d_in[5];
    const float* q_w  = (const float*)d_in[6];
    const float* q_b  = (const float*)d_in[7];
    const float* kv_w = (const float*)d_in[8];
    const float* kv_b = (const float*)d_in[9];
    const float* rpb  = (const float*)d_in[10];
    const float* p_w  = (const float*)d_in[11];
    const float* p_b  = (const float*)d_in[12];
    const float* n2g  = (const float*)d_in[13];
    const float* n2b  = (const float*)d_in[14];
    const float* w1   = (const float*)d_in[15];
    const float* b1   = (const float*)d_in[16];
    const float* w2   = (const float*)d_in[17];
    const float* b2   = (const float*)d_in[18];
    float* out = (float*)d_out;

    float *p_xn, *p_q, *p_kv, *p_ao, *p_xo, *p_xn2, *p_mh;
    cudaGetSymbolAddress((void**)&p_xn,  g_xn);
    cudaGetSymbolAddress((void**)&p_q,   g_q);
    cudaGetSymbolAddress((void**)&p_kv,  g_kv);
    cudaGetSymbolAddress((void**)&p_ao,  g_ao);
    cudaGetSymbolAddress((void**)&p_xo,  g_xo);
    cudaGetSymbolAddress((void**)&p_xn2, g_xn2);
    cudaGetSymbolAddress((void**)&p_mh,  g_mh);

    cudaFuncSetAttribute(mma_gemm<0>, cudaFuncAttributeMaxDynamicSharedMemorySize, GEMM_SMEM);
    cudaFuncSetAttribute(mma_gemm<1>, cudaFuncAttributeMaxDynamicSharedMemorySize, GEMM_SMEM);

    dim3 lnBlk(32, 8);

    // 1. xn = LN(x)
    ln_kernel<<<NPIX / 8, lnBlk>>>(x, n1g, n1b, p_xn);
    // 2. bias table (transposed [h][k][q])
    bias_kernel<<<NKEY, NQ>>>(rpi, rpb);
    // 3. q = xn @ q_w + q_b
    mma_gemm<0><<<dim3(3, NPIX / 128), 256, GEMM_SMEM>>>(p_xn, q_w, q_b, nullptr, p_q, NPIX, CDIM, CDIM);
    // 4. kv = xn @ kv_w + kv_b
    mma_gemm<0><<<dim3(6, NPIX / 128), 256, GEMM_SMEM>>>(p_xn, kv_w, kv_b, nullptr, p_kv, NPIX, 2 * CDIM, CDIM);
    // 5. windowed attention -> g_ao (pixel-major)
    attn_kernel<<<dim3(NWIN * NWIN, NHEADS), 256>>>();
    // 6. xo = ao @ proj_w + proj_b + x
    mma_gemm<0><<<dim3(3, NPIX / 128), 256, GEMM_SMEM>>>(p_ao, p_w, p_b, x, p_xo, NPIX, CDIM, CDIM);
    // 7. xn2 = LN(xo)
    ln_kernel<<<NPIX / 8, lnBlk>>>(p_xo, n2g, n2b, p_xn2);
    // 8. mh = gelu(xn2 @ w1 + b1)
    mma_gemm<1><<<dim3(6, NPIX / 128), 256, GEMM_SMEM>>>(p_xn2, w1, b1, nullptr, p_mh, NPIX, MLPH, CDIM);
    // 9. out = mh @ w2 + b2 + xo
    mma_gemm<0><<<dim3(3, NPIX / 128), 256, GEMM_SMEM>>>(p_mh, w2, b2, p_xo, out, NPIX, CDIM, MLPH);
}

// round 7
// speedup vs baseline: 3.0312x; 3.0312x over previous
#include <cuda_runtime.h>
#include <cuda_bf16.h>
#include <math.h>

// ---------------- problem constants ----------------
#define HIMG 256
#define WIMG 256
#define NPIX 65536            // HIMG*WIMG
#define CDIM 180
#define NHEADS 6
#define HD 30                 // CDIM / NHEADS
#define WS 16
#define OWS 24
#define PADW 4                // (OWS-WS)/2
#define NWIN 16               // windows per side
#define NQ 256                // WS*WS
#define NKEY 576              // OWS*OWS
#define MLPH 360

// ---------------- scratch (device globals; no allocation allowed) ----------------
__device__ float g_xn [NPIX*CDIM];
__device__ float g_q  [NPIX*CDIM];
__device__ float g_kv [NPIX*2*CDIM];
__device__ float g_biasQ[NHEADS*NQ*NKEY];   // [head][query][key]
__device__ float g_ao [NPIX*CDIM];
__device__ float g_xo [NPIX*CDIM];
__device__ float g_xn2[NPIX*CDIM];
__device__ float g_mh [NPIX*MLPH];

// ---------------- LayerNorm: one warp per row of 180 ----------------
__global__ void ln_kernel(const float* __restrict__ x, const float* __restrict__ g,
                          const float* __restrict__ b, float* __restrict__ y) {
    int row  = blockIdx.x * blockDim.y + threadIdx.y;
    int lane = threadIdx.x;
    const float* xr = x + (size_t)row * CDIM;
    float v[6];
    float s = 0.f;
#pragma unroll
    for (int i = 0; i < 6; i++) {
        int d = lane + 32 * i;
        v[i] = (d < CDIM) ? xr[d] : 0.f;
        s += v[i];
    }
#pragma unroll
    for (int o = 16; o > 0; o >>= 1) s += __shfl_xor_sync(0xffffffffu, s, o);
    float mu = s * (1.f / CDIM);
    float vs = 0.f;
#pragma unroll
    for (int i = 0; i < 6; i++) {
        int d = lane + 32 * i;
        float dv = (d < CDIM) ? (v[i] - mu) : 0.f;
        vs += dv * dv;
    }
#pragma unroll
    for (int o = 16; o > 0; o >>= 1) vs += __shfl_xor_sync(0xffffffffu, vs, o);
    float inv = rsqrtf(vs * (1.f / CDIM) + 1e-5f);
    float* yr = y + (size_t)row * CDIM;
#pragma unroll
    for (int i = 0; i < 6; i++) {
        int d = lane + 32 * i;
        if (d < CDIM) yr[d] = g[d] * (v[i] - mu) * inv + b[d];
    }
}

// ---------------- bias precompute: biasQ[h][q][k] = table[rpi[q,k], h] ----------------
__global__ void bias_kernel(const int* __restrict__ rpi, const float* __restrict__ table) {
    int q = blockIdx.x;       // 0..255
    int k = threadIdx.x;      // 0..575
    int t = rpi[q * NKEY + k];
#pragma unroll
    for (int h = 0; h < NHEADS; h++)
        g_biasQ[((size_t)h * NQ + q) * NKEY + k] = table[t * NHEADS + h];
}

// ---------------- tf32 tensor-core GEMM, double-buffered, paired smem ----------------
__device__ __forceinline__ unsigned f2tf32(float v) {
    unsigned u;
    asm("cvt.rna.tf32.f32 %0, %1;" : "=r"(u) : "f"(v));
    return u;
}

#define AS_T  132
#define AS_KS 532
#define ABUF  2128      // 4*AS_KS (uint2)
#define BS_T  68
#define BS_KS 273
#define BBUF  1092      // 4*BS_KS (uint2)
#define STGSZ (ABUF + BBUF)               // 3220 uint2 per stage
#define GEMM_SMEM (2 * STGSZ * 8)         // 51520 bytes

template<int ACT>
__global__ void __launch_bounds__(256, 2) mma_gemm(
    const float* __restrict__ A, const float* __restrict__ B,
    const float* __restrict__ bias, const float* __restrict__ res,
    float* __restrict__ C, int M, int N, int K)
{
    extern __shared__ uint2 smbuf[];

    int bm = blockIdx.y * 128;
    int bn = blockIdx.x * 64;
    int t    = threadIdx.x;
    int lane = t & 31;
    int warp = t >> 5;
    int g  = lane >> 2;
    int tq = lane & 3;
    int wm = (warp >> 1) * 32;
    int wn = (warp & 1) * 32;

    float acc[2][4][4];
#pragma unroll
    for (int mi = 0; mi < 2; mi++)
#pragma unroll
        for (int ni = 0; ni < 4; ni++)
#pragma unroll
            for (int r = 0; r < 4; r++) acc[mi][ni][r] = 0.f;

    int kIters = (K + 31) >> 5;
    float4 ra[4], rb[2];

    auto gload = [&](int it) {
        int k0 = it * 32;
#pragma unroll
        for (int i = 0; i < 4; i++) {
            int idx = t + 256 * i;
            int m = idx >> 3, j = idx & 7;
            int gk = k0 + 4 * j;
            ra[i] = (gk < K) ? *(const float4*)&A[(size_t)(bm + m) * K + gk]
                             : make_float4(0.f, 0.f, 0.f, 0.f);
        }
#pragma unroll
        for (int i = 0; i < 2; i++) {
            int idx = t + 256 * i;
            int k = idx & 31, n = 4 * (idx >> 5);
            int gk = k0 + k, gn = bn + n;
            rb[i] = (gk < K && gn < N) ? *(const float4*)&B[(size_t)gk * N + gn]
                                       : make_float4(0.f, 0.f, 0.f, 0.f);
        }
    };

    auto sstore = [&](int s) {
        unsigned* ab = (unsigned*)(smbuf + s * STGSZ);
        unsigned* bb = (unsigned*)(smbuf + s * STGSZ + ABUF);
#pragma unroll
        for (int i = 0; i < 4; i++) {
            int idx = t + 256 * i;
            int m = idx >> 3, j = idx & 7;
            int ks = j >> 1, sel = j & 1;
            unsigned base = 2 * (ks * AS_KS + m) + sel;
            ab[base + 2 * (0 * AS_T)] = f2tf32(ra[i].x);
            ab[base + 2 * (1 * AS_T)] = f2tf32(ra[i].y);
            ab[base + 2 * (2 * AS_T)] = f2tf32(ra[i].z);
            ab[base + 2 * (3 * AS_T)] = f2tf32(ra[i].w);
        }
#pragma unroll
        for (int i = 0; i < 2; i++) {
            int idx = t + 256 * i;
            int k = idx & 31, n = 4 * (idx >> 5);
            int ks = k >> 3, tqq = k & 3, sel = (k >> 2) & 1;
            unsigned base = 2 * (ks * BS_KS + tqq * BS_T + n) + sel;
            bb[base + 0] = f2tf32(rb[i].x);
            bb[base + 2] = f2tf32(rb[i].y);
            bb[base + 4] = f2tf32(rb[i].z);
            bb[base + 6] = f2tf32(rb[i].w);
        }
    };

    auto compute = [&](int s) {
        const uint2* as = smbuf + s * STGSZ;
        const uint2* bs = as + ABUF;
#pragma unroll
        for (int ks = 0; ks < 4; ks++) {
            uint2 aLo[2], aHi[2], bp[4];
#pragma unroll
            for (int mi = 0; mi < 2; mi++) {
                int m0 = wm + mi * 16 + g;
                aLo[mi] = as[ks * AS_KS + tq * AS_T + m0];
                aHi[mi] = as[ks * AS_KS + tq * AS_T + m0 + 8];
            }
#pragma unroll
            for (int ni = 0; ni < 4; ni++)
                bp[ni] = bs[ks * BS_KS + tq * BS_T + wn + ni * 8 + g];
#pragma unroll
            for (int mi = 0; mi < 2; mi++)
#pragma unroll
                for (int ni = 0; ni < 4; ni++) {
                    asm volatile(
                        "mma.sync.aligned.m16n8k8.row.col.f32.tf32.tf32.f32 "
                        "{%0,%1,%2,%3}, {%4,%5,%6,%7}, {%8,%9}, {%0,%1,%2,%3};"
                        : "+f"(acc[mi][ni][0]), "+f"(acc[mi][ni][1]),
                          "+f"(acc[mi][ni][2]), "+f"(acc[mi][ni][3])
                        : "r"(aLo[mi].x), "r"(aHi[mi].x),
                          "r"(aLo[mi].y), "r"(aHi[mi].y),
                          "r"(bp[ni].x), "r"(bp[ni].y));
                }
        }
    };

    gload(0);
    sstore(0);
    __syncthreads();
    for (int it = 0; it < kIters; it++) {
        if (it + 1 < kIters) gload(it + 1);
        compute(it & 1);
        if (it + 1 < kIters) {
            sstore((it + 1) & 1);
            __syncthreads();
        }
    }

#pragma unroll
    for (int mi = 0; mi < 2; mi++) {
#pragma unroll
        for (int ni = 0; ni < 4; ni++) {
            int n = bn + wn + ni * 8 + 2 * tq;
            if (n >= N) continue;
            float bn0 = bias[n], bn1 = bias[n + 1];
#pragma unroll
            for (int half = 0; half < 2; half++) {
                int m = bm + wm + mi * 16 + g + half * 8;
                float v0 = acc[mi][ni][half * 2 + 0] + bn0;
                float v1 = acc[mi][ni][half * 2 + 1] + bn1;
                if (res) {
                    v0 += res[(size_t)m * N + n];
                    v1 += res[(size_t)m * N + n + 1];
                }
                if (ACT == 1) {
                    v0 = v0 * normcdff(v0);
                    v1 = v1 * normcdff(v1);
                }
                C[(size_t)m * N + n]     = v0;
                C[(size_t)m * N + n + 1] = v1;
            }
        }
    }
}

// ---------------- bf16 tensor-core windowed attention ----------------
// grid (256 windows, 6 heads), 256 threads = 8 warps, each warp owns 32 query
// rows. 9 chunks of 64 keys, flash-style accumulation without max-subtraction
// (scores |s| << 1). OOB keys are staged as zeros -> contribute exp(bias) to
// the denominator with v=0, matching the reference's pad-then-softmax.
// QK and PV both use mma.m16n8k16.bf16; the packed bf16x2 P registers are
// exactly the A-fragment layout of the PV mma (no shuffles).
// VsT has 32 rows: rows 30/31 are zeroed and feed only the discarded output
// columns 30/31 of the PV mma (they must be in-bounds — R6's [30] rows trapped).
__device__ __forceinline__ void mma_bf16(float* c, unsigned a0, unsigned a1,
                                         unsigned a2, unsigned a3,
                                         unsigned b0, unsigned b1) {
    asm volatile(
        "mma.sync.aligned.m16n8k16.row.col.f32.bf16.bf16.f32 "
        "{%0,%1,%2,%3}, {%4,%5,%6,%7}, {%8,%9}, {%0,%1,%2,%3};"
        : "+f"(c[0]), "+f"(c[1]), "+f"(c[2]), "+f"(c[3])
        : "r"(a0), "r"(a1), "r"(a2), "r"(a3), "r"(b0), "r"(b1));
}

__global__ void __launch_bounds__(256, 2) attn_mma_kernel() {
    int win  = blockIdx.x;
    int head = blockIdx.y;
    int wi = win >> 4, wj = win & 15;
    int t    = threadIdx.x;
    int lane = t & 31;
    int warp = t >> 5;
    int g  = lane >> 2;
    int tq = lane & 3;
    int wq = warp * 32;

    // Row strides chosen so fragment loads hit all 32 banks:
    // Qs/Ks stride 40 bf16 (20 words): bank = 20g+tq -> 32 distinct.
    // VsT stride 72 bf16 (36 words): bank = 4g+8ks+tq -> 32 distinct.
    __shared__ __nv_bfloat16 Qs[NQ][40];    // 20480 B
    __shared__ __nv_bfloat16 Ks[64][40];    //  5120 B
    __shared__ __nv_bfloat16 VsT[32][72];   //  4608 B (rows 30/31 zeroed)

    const float scale = 0.18257418583505537f;  // 30^-0.5

    // ---- stage Q (once): row t = query pixel; fold scale; zero pad dims ----
    {
        int qi = t >> 4, qj = t & 15;
        int pix = (wi * WS + qi) * WIMG + (wj * WS + qj);
        const float* src = g_q + (size_t)pix * CDIM + head * HD;
#pragma unroll
        for (int j = 0; j < 15; j++) {
            float2 v = *(const float2*)&src[2 * j];
            *(__nv_bfloat162*)&Qs[t][2 * j] =
                __floats2bfloat162_rn(v.x * scale, v.y * scale);
        }
        *(__nv_bfloat162*)&Qs[t][30] = __floats2bfloat162_rn(0.f, 0.f);
    }
    __syncthreads();

    // ---- persistent Q A-fragments ----
    unsigned aq[2][2][4];
#pragma unroll
    for (int mi = 0; mi < 2; mi++) {
        int q0 = wq + mi * 16 + g, q1 = q0 + 8;
#pragma unroll
        for (int ks = 0; ks < 2; ks++) {
            int c0 = ks * 16 + 2 * tq;
            aq[mi][ks][0] = *(const unsigned*)&Qs[q0][c0];
            aq[mi][ks][1] = *(const unsigned*)&Qs[q1][c0];
            aq[mi][ks][2] = *(const unsigned*)&Qs[q0][c0 + 8];
            aq[mi][ks][3] = *(const unsigned*)&Qs[q1][c0 + 8];
        }
    }

    float O[2][4][4];
#pragma unroll
    for (int mi = 0; mi < 2; mi++)
#pragma unroll
        for (int nj = 0; nj < 4; nj++)
#pragma unroll
            for (int r = 0; r < 4; r++) O[mi][nj][r] = 0.f;
    float l0[2] = {0.f, 0.f}, l1[2] = {0.f, 0.f};

    int half  = t >> 7;         // 0: stage K, 1: stage V
    int key_l = (t & 127) >> 1; // key within chunk
    int part  = t & 1;          // which 15-dim half

    for (int ch = 0; ch < 9; ch++) {
        int cb = ch * 64;
        __syncthreads();
        // ---- stage K chunk -> Ks[key][d], V chunk -> VsT[d][key] (bf16) ----
        {
            int key = cb + key_l;
            int ki = key / OWS;
            int kj = key - ki * OWS;
            int gr = wi * WS - PADW + ki;
            int gc = wj * WS - PADW + kj;
            bool ok = ((unsigned)gr < HIMG) && ((unsigned)gc < WIMG);
            const float* src = g_kv + ((size_t)(gr * WIMG + gc)) * (2 * CDIM)
                               + half * CDIM + head * HD + part * 15;
            if (half == 0) {
#pragma unroll
                for (int d = 0; d < 15; d++)
                    Ks[key_l][part * 15 + d] = __float2bfloat16(ok ? src[d] : 0.f);
                if (part == 0)
                    *(__nv_bfloat162*)&Ks[key_l][30] = __floats2bfloat162_rn(0.f, 0.f);
            } else {
#pragma unroll
                for (int d = 0; d < 15; d++)
                    VsT[part * 15 + d][key_l] = __float2bfloat16(ok ? src[d] : 0.f);
                if (part == 0) {
                    VsT[30][key_l] = __float2bfloat16(0.f);
                    VsT[31][key_l] = __float2bfloat16(0.f);
                }
            }
        }
        __syncthreads();

        // ---- S = Q K^T + bias, p = exp(S), pack P in bf16x2 A-frag layout ----
        unsigned P[2][8][2];
#pragma unroll
        for (int mi = 0; mi < 2; mi++) {
            int q0 = wq + mi * 16 + g, q1 = q0 + 8;
            const float* bp0 = g_biasQ + ((size_t)head * NQ + q0) * NKEY + cb + 2 * tq;
            const float* bp1 = g_biasQ + ((size_t)head * NQ + q1) * NKEY + cb + 2 * tq;
#pragma unroll
            for (int ni = 0; ni < 8; ni++) {
                float c[4] = {0.f, 0.f, 0.f, 0.f};
                int krow = ni * 8 + g;
#pragma unroll
                for (int ks = 0; ks < 2; ks++) {
                    unsigned b0 = *(const unsigned*)&Ks[krow][ks * 16 + 2 * tq];
                    unsigned b1 = *(const unsigned*)&Ks[krow][ks * 16 + 2 * tq + 8];
                    mma_bf16(c, aq[mi][ks][0], aq[mi][ks][1], aq[mi][ks][2], aq[mi][ks][3], b0, b1);
                }
                float2 bA = *(const float2*)&bp0[ni * 8];
                float2 bB = *(const float2*)&bp1[ni * 8];
                float p0 = __expf(c[0] + bA.x);
                float p1 = __expf(c[1] + bA.y);
                float p2 = __expf(c[2] + bB.x);
                float p3 = __expf(c[3] + bB.y);
                l0[mi] += p0 + p1;
                l1[mi] += p2 + p3;
                __nv_bfloat162 h0 = __floats2bfloat162_rn(p0, p1);
                __nv_bfloat162 h1 = __floats2bfloat162_rn(p2, p3);
                P[mi][ni][0] = *(unsigned*)&h0;
                P[mi][ni][1] = *(unsigned*)&h1;
            }
        }

        // ---- O += P V ----
#pragma unroll
        for (int mi = 0; mi < 2; mi++)
#pragma unroll
            for (int nj = 0; nj < 4; nj++) {
                int drow = nj * 8 + g;   // 0..31, always in-bounds of VsT
#pragma unroll
                for (int ks = 0; ks < 4; ks++) {
                    unsigned b0 = *(const unsigned*)&VsT[drow][ks * 16 + 2 * tq];
                    unsigned b1 = *(const unsigned*)&VsT[drow][ks * 16 + 2 * tq + 8];
                    mma_bf16(O[mi][nj],
                             P[mi][2 * ks][0], P[mi][2 * ks][1],
                             P[mi][2 * ks + 1][0], P[mi][2 * ks + 1][1],
                             b0, b1);
                }
            }
    }

    // ---- finalize: reduce l over the quad, normalize, write out ----
#pragma unroll
    for (int mi = 0; mi < 2; mi++) {
        l0[mi] += __shfl_xor_sync(0xffffffffu, l0[mi], 1);
        l0[mi] += __shfl_xor_sync(0xffffffffu, l0[mi], 2);
        l1[mi] += __shfl_xor_sync(0xffffffffu, l1[mi], 1);
        l1[mi] += __shfl_xor_sync(0xffffffffu, l1[mi], 2);
    }
#pragma unroll
    for (int mi = 0; mi < 2; mi++) {
        float inv0 = 1.f / l0[mi];
        float inv1 = 1.f / l1[mi];
        int q0 = wq + mi * 16 + g, q1 = q0 + 8;
        int pix0 = (wi * WS + (q0 >> 4)) * WIMG + (wj * WS + (q0 & 15));
        int pix1 = (wi * WS + (q1 >> 4)) * WIMG + (wj * WS + (q1 & 15));
        float* o0 = g_ao + (size_t)pix0 * CDIM + head * HD;
        float* o1 = g_ao + (size_t)pix1 * CDIM + head * HD;
#pragma unroll
        for (int nj = 0; nj < 4; nj++) {
            int d = nj * 8 + 2 * tq;
            if (d < HD) {
                *(float2*)&o0[d] = make_float2(O[mi][nj][0] * inv0, O[mi][nj][1] * inv0);
                *(float2*)&o1[d] = make_float2(O[mi][nj][2] * inv1, O[mi][nj][3] * inv1);
            }
        }
    }
}

// ---------------- launch ----------------
extern "C" void kernel_launch(void* const* d_in, const int* in_sizes, int n_in,
                              void* d_out, int out_size) {
    const float* x    = (const float*)d_in[0];
    const int*   rpi  = (const int*)  d_in[1];
    const float* n1g  = (const float*)d_in[4];
    const float* n1b  = (const float*)d_in[5];
    const float* q_w  = (const float*)d_in[6];
    const float* q_b  = (const float*)d_in[7];
    const float* kv_w = (const float*)d_in[8];
    const float* kv_b = (const float*)d_in[9];
    const float* rpb  = (const float*)d_in[10];
    const float* p_w  = (const float*)d_in[11];
    const float* p_b  = (const float*)d_in[12];
    const float* n2g  = (const float*)d_in[13];
    const float* n2b  = (const float*)d_in[14];
    const float* w1   = (const float*)d_in[15];
    const float* b1   = (const float*)d_in[16];
    const float* w2   = (const float*)d_in[17];
    const float* b2   = (const float*)d_in[18];
    float* out = (float*)d_out;

    float *p_xn, *p_q, *p_kv, *p_ao, *p_xo, *p_xn2, *p_mh;
    cudaGetSymbolAddress((void**)&p_xn,  g_xn);
    cudaGetSymbolAddress((void**)&p_q,   g_q);
    cudaGetSymbolAddress((void**)&p_kv,  g_kv);
    cudaGetSymbolAddress((void**)&p_ao,  g_ao);
    cudaGetSymbolAddress((void**)&p_xo,  g_xo);
    cudaGetSymbolAddress((void**)&p_xn2, g_xn2);
    cudaGetSymbolAddress((void**)&p_mh,  g_mh);

    cudaFuncSetAttribute(mma_gemm<0>, cudaFuncAttributeMaxDynamicSharedMemorySize, GEMM_SMEM);
    cudaFuncSetAttribute(mma_gemm<1>, cudaFuncAttributeMaxDynamicSharedMemorySize, GEMM_SMEM);

    dim3 lnBlk(32, 8);

    // 1. xn = LN(x)
    ln_kernel<<<NPIX / 8, lnBlk>>>(x, n1g, n1b, p_xn);
    // 2. bias table ([head][q][k] layout)
    bias_kernel<<<NQ, NKEY>>>(rpi, rpb);
    // 3. q = xn @ q_w + q_b
    mma_gemm<0><<<dim3(3, NPIX / 128), 256, GEMM_SMEM>>>(p_xn, q_w, q_b, nullptr, p_q, NPIX, CDIM, CDIM);
    // 4. kv = xn @ kv_w + kv_b
    mma_gemm<0><<<dim3(6, NPIX / 128), 256, GEMM_SMEM>>>(p_xn, kv_w, kv_b, nullptr, p_kv, NPIX, 2 * CDIM, CDIM);
    // 5. windowed attention (bf16 tensor cores) -> g_ao
    attn_mma_kernel<<<dim3(NWIN * NWIN, NHEADS), 256>>>();
    // 6. xo = ao @ proj_w + proj_b + x
    mma_gemm<0><<<dim3(3, NPIX / 128), 256, GEMM_SMEM>>>(p_ao, p_w, p_b, x, p_xo, NPIX, CDIM, CDIM);
    // 7. xn2 = LN(xo)
    ln_kernel<<<NPIX / 8, lnBlk>>>(p_xo, n2g, n2b, p_xn2);
    // 8. mh = gelu(xn2 @ w1 + b1)
    mma_gemm<1><<<dim3(6, NPIX / 128), 256, GEMM_SMEM>>>(p_xn2, w1, b1, nullptr, p_mh, NPIX, MLPH, CDIM);
    // 9. out = mh @ w2 + b2 + xo
    mma_gemm<0><<<dim3(3, NPIX / 128), 256, GEMM_SMEM>>>(p_mh, w2, b2, p_xo, out, NPIX, CDIM, MLPH);
}